// round 7
// baseline (speedup 1.0000x reference)
#include <cuda_runtime.h>
#include <math.h>
#include <stdint.h>

// Problem constants
constexpr int NN   = 30000;      // nodes
constexpr int EE   = 240000;     // edges (before self loops)
constexpr int GG   = 1000;       // graphs
constexpr int FF   = 78;         // in features
constexpr int HH   = 10;         // GAT heads
constexpr int HIDC = 780;        // F*H
constexpr int ET   = EE + NN;    // edges with self loops
constexpr int P1   = 1500;       // fc1 width
constexpr int PO   = 2 * HIDC;   // pooled width 1560
constexpr int OC   = 128;        // output classes
constexpr int H4   = HIDC / 4;   // 195 float4 per feature row

// ---- one big device scratch buffer (no allocations allowed) ----
constexpr size_t OFF_H    = 0;
constexpr size_t OFF_OUT1 = OFF_H    + (size_t)NN * HIDC;
constexpr size_t OFF_H2   = OFF_OUT1 + (size_t)NN * HIDC;
constexpr size_t OFF_OUT2 = OFF_H2   + (size_t)NN * HIDC;
constexpr size_t OFF_ASRC = OFF_OUT2 + (size_t)NN * HIDC;
constexpr size_t OFF_ADST = OFF_ASRC + (size_t)NN * HH;
constexpr size_t OFF_DINV = OFF_ADST + (size_t)NN * HH;
constexpr size_t OFF_POOL = OFF_DINV + NN;
constexpr size_t OFF_FC1  = OFF_POOL + (size_t)GG * PO;
constexpr size_t OFF_DEG  = OFF_FC1  + (size_t)GG * P1;
constexpr size_t OFF_ROWP = OFF_DEG  + NN;
constexpr size_t OFF_WPTR = OFF_ROWP + NN + 1;
constexpr size_t OFF_CSRC = OFF_WPTR + NN;
constexpr size_t OFF_CNT  = OFF_CSRC + ET;
constexpr size_t OFF_GST  = OFF_CNT  + GG;
constexpr size_t TOTALF   = OFF_GST  + GG + 1;

__device__ __align__(16) float g_buf[TOTALF];

// ============================================================
// helpers
// ============================================================
__device__ __forceinline__ uint32_t f2tf32(float v)
{
    uint32_t r;
    asm("cvt.rna.tf32.f32 %0, %1;" : "=r"(r) : "f"(v));
    return r;
}

__device__ __forceinline__ void mma_tf32(float c[4],
                                         const uint32_t a[4],
                                         const uint32_t b[2])
{
    asm volatile(
        "mma.sync.aligned.m16n8k8.row.col.f32.tf32.tf32.f32 "
        "{%0,%1,%2,%3}, {%4,%5,%6,%7}, {%8,%9}, {%0,%1,%2,%3};"
        : "+f"(c[0]), "+f"(c[1]), "+f"(c[2]), "+f"(c[3])
        : "r"(a[0]), "r"(a[1]), "r"(a[2]), "r"(a[3]),
          "r"(b[0]), "r"(b[1]));
}

__device__ __forceinline__ void cp_async16(void* smem_dst, const void* gsrc, int nbytes)
{
    uint32_t d = (uint32_t)__cvta_generic_to_shared(smem_dst);
    asm volatile("cp.async.cg.shared.global [%0], [%1], 16, %2;"
                 :: "r"(d), "l"(gsrc), "r"(nbytes));
}
__device__ __forceinline__ void cp_async8(void* smem_dst, const void* gsrc, int nbytes)
{
    uint32_t d = (uint32_t)__cvta_generic_to_shared(smem_dst);
    asm volatile("cp.async.ca.shared.global [%0], [%1], 8, %2;"
                 :: "r"(d), "l"(gsrc), "r"(nbytes));
}
__device__ __forceinline__ void cp_commit() { asm volatile("cp.async.commit_group;"); }
template<int N> __device__ __forceinline__ void cp_wait()
{ asm volatile("cp.async.wait_group %0;" :: "n"(N)); }

// ============================================================
// Pipelined TF32 GEMM: C[M,Nc] = A[M,K] @ B[K,Nc] (+bias)(+relu)
// 128x128 block tile, BK=16, double-buffered cp.async, 256 thr.
// REQUIRES: K % 4 == 0, Nc % 4 == 0.
// ============================================================
template<bool BIAS, bool RELU>
__global__ __launch_bounds__(256, 2)
void tf32_gemm_pipe(const float* __restrict__ A, const float* __restrict__ B,
                    const float* __restrict__ bias, float* __restrict__ C,
                    int M, int K, int Nc)
{
    __shared__ __align__(16) float As[2][128][20];
    __shared__ __align__(16) float Bs[2][16][136];

    const int tid  = threadIdx.x;
    const int warp = tid >> 5, lane = tid & 31;
    const int gid  = lane >> 2, tg = lane & 3;
    const int wr   = warp >> 2, wc = warp & 3;        // 2 x 4 warp grid
    const int m0   = blockIdx.y * 128, n0 = blockIdx.x * 128;

    const int a_row = tid >> 1;            // 0..127
    const int a_c0  = (tid & 1) * 8;       // 0 or 8
    const int b_r   = tid >> 4;            // 0..15
    const int b_c0  = (tid & 15) * 8;      // 0..120

    const int gmA = m0 + a_row;
    const float* a_base = A + (size_t)(gmA < M ? gmA : M - 1) * K;
    const bool a_rowok = (gmA < M);

    float acc[4][4][4];
#pragma unroll
    for (int i = 0; i < 4; i++)
#pragma unroll
        for (int j = 0; j < 4; j++)
#pragma unroll
            for (int k = 0; k < 4; k++) acc[i][j][k] = 0.f;

    const int nk = (K + 15) / 16;

    auto load_tile = [&](int buf, int k0) {
#pragma unroll
        for (int ch = 0; ch < 2; ch++) {
            int c = a_c0 + ch * 4;
            int gk = k0 + c;
            bool ok = a_rowok && (gk + 4 <= K);
            const float* src = a_base + (gk + 4 <= K ? gk : 0);
            cp_async16(&As[buf][a_row][c], src, ok ? 16 : 0);
        }
        int gkB = k0 + b_r;
        const float* b_base = B + (size_t)(gkB < K ? gkB : K - 1) * Nc;
#pragma unroll
        for (int ch = 0; ch < 2; ch++) {
            int c = b_c0 + ch * 4;
            int gn = n0 + c;
            bool ok = (gkB < K) && (gn + 4 <= Nc);
            const float* src = b_base + (gn + 4 <= Nc ? gn : 0);
            cp_async16(&Bs[buf][b_r][c], src, ok ? 16 : 0);
        }
    };

    load_tile(0, 0);
    cp_commit();

    for (int t = 0; t < nk; t++) {
        int buf = t & 1;
        if (t + 1 < nk) load_tile(buf ^ 1, (t + 1) * 16);
        cp_commit();
        cp_wait<1>();
        __syncthreads();

#pragma unroll
        for (int ks = 0; ks < 16; ks += 8) {
            uint32_t af[4][4];
#pragma unroll
            for (int mt = 0; mt < 4; mt++) {
                int m = wr * 64 + mt * 16;
                af[mt][0] = f2tf32(As[buf][m + gid    ][ks + tg    ]);
                af[mt][1] = f2tf32(As[buf][m + gid + 8][ks + tg    ]);
                af[mt][2] = f2tf32(As[buf][m + gid    ][ks + tg + 4]);
                af[mt][3] = f2tf32(As[buf][m + gid + 8][ks + tg + 4]);
            }
            uint32_t bf[4][2];
#pragma unroll
            for (int nt = 0; nt < 4; nt++) {
                int n = wc * 32 + nt * 8 + gid;
                bf[nt][0] = f2tf32(Bs[buf][ks + tg    ][n]);
                bf[nt][1] = f2tf32(Bs[buf][ks + tg + 4][n]);
            }
#pragma unroll
            for (int mt = 0; mt < 4; mt++)
#pragma unroll
                for (int nt = 0; nt < 4; nt++)
                    mma_tf32(acc[mt][nt], af[mt], bf[nt]);
        }
        __syncthreads();
    }

#pragma unroll
    for (int mt = 0; mt < 4; mt++) {
        int rm = m0 + wr * 64 + mt * 16 + gid;
#pragma unroll
        for (int nt = 0; nt < 4; nt++) {
            int cn = n0 + wc * 32 + nt * 8 + 2 * tg;
#pragma unroll
            for (int half = 0; half < 2; half++) {
                int r = rm + half * 8;
                if (r >= M) continue;
                float v0 = acc[mt][nt][half * 2 + 0];
                float v1 = acc[mt][nt][half * 2 + 1];
                if (cn < Nc) {
                    float v = v0;
                    if (BIAS) v += bias[cn];
                    if (RELU) v = v > 0.f ? v : 0.f;
                    C[(size_t)r * Nc + cn] = v;
                }
                if (cn + 1 < Nc) {
                    float v = v1;
                    if (BIAS) v += bias[cn + 1];
                    if (RELU) v = v > 0.f ? v : 0.f;
                    C[(size_t)r * Nc + cn + 1] = v;
                }
            }
        }
    }
}

// ============================================================
// Split-TF32 ("3xTF32") GEMM: fp32-level accuracy on tensor pipe.
// acc += hi_a*hi_b + hi_a*lo_b + lo_a*hi_b.
// A rows only need 8B alignment (K % 2 == 0); Nc % 4 == 0.
// Used for the GAT linear layer (feeds the attention softmax).
// ============================================================
__global__ __launch_bounds__(256)
void tf32_gemm_split(const float* __restrict__ A, const float* __restrict__ B,
                     float* __restrict__ C, int M, int K, int Nc)
{
    __shared__ __align__(16) float As[2][128][20];
    __shared__ __align__(16) float Bs[2][16][136];

    const int tid  = threadIdx.x;
    const int warp = tid >> 5, lane = tid & 31;
    const int gid  = lane >> 2, tg = lane & 3;
    const int wr   = warp >> 2, wc = warp & 3;
    const int m0   = blockIdx.y * 128, n0 = blockIdx.x * 128;

    const int a_row = tid >> 1;
    const int a_c0  = (tid & 1) * 8;
    const int b_r   = tid >> 4;
    const int b_c0  = (tid & 15) * 8;

    const int gmA = m0 + a_row;
    const float* a_base = A + (size_t)(gmA < M ? gmA : M - 1) * K;
    const bool a_rowok = (gmA < M);

    float acc[4][4][4];
#pragma unroll
    for (int i = 0; i < 4; i++)
#pragma unroll
        for (int j = 0; j < 4; j++)
#pragma unroll
            for (int k = 0; k < 4; k++) acc[i][j][k] = 0.f;

    const int nk = (K + 15) / 16;

    auto load_tile = [&](int buf, int k0) {
        // A via 8-byte chunks (row stride only 8B-aligned for odd K/2)
#pragma unroll
        for (int ch = 0; ch < 4; ch++) {
            int c = a_c0 + ch * 2;
            int gk = k0 + c;
            bool ok = a_rowok && (gk + 2 <= K);
            const float* src = a_base + (gk + 2 <= K ? gk : 0);
            cp_async8(&As[buf][a_row][c], src, ok ? 8 : 0);
        }
        int gkB = k0 + b_r;
        const float* b_base = B + (size_t)(gkB < K ? gkB : K - 1) * Nc;
#pragma unroll
        for (int ch = 0; ch < 2; ch++) {
            int c = b_c0 + ch * 4;
            int gn = n0 + c;
            bool ok = (gkB < K) && (gn + 4 <= Nc);
            const float* src = b_base + (gn + 4 <= Nc ? gn : 0);
            cp_async16(&Bs[buf][b_r][c], src, ok ? 16 : 0);
        }
    };

    load_tile(0, 0);
    cp_commit();

    for (int t = 0; t < nk; t++) {
        int buf = t & 1;
        if (t + 1 < nk) load_tile(buf ^ 1, (t + 1) * 16);
        cp_commit();
        cp_wait<1>();
        __syncthreads();

#pragma unroll
        for (int ks = 0; ks < 16; ks += 8) {
            uint32_t ah[4][4], al[4][4];
#pragma unroll
            for (int mt = 0; mt < 4; mt++) {
                int m = wr * 64 + mt * 16;
                float v0 = As[buf][m + gid    ][ks + tg    ];
                float v1 = As[buf][m + gid + 8][ks + tg    ];
                float v2 = As[buf][m + gid    ][ks + tg + 4];
                float v3 = As[buf][m + gid + 8][ks + tg + 4];
                ah[mt][0] = f2tf32(v0); al[mt][0] = f2tf32(v0 - __uint_as_float(ah[mt][0]));
                ah[mt][1] = f2tf32(v1); al[mt][1] = f2tf32(v1 - __uint_as_float(ah[mt][1]));
                ah[mt][2] = f2tf32(v2); al[mt][2] = f2tf32(v2 - __uint_as_float(ah[mt][2]));
                ah[mt][3] = f2tf32(v3); al[mt][3] = f2tf32(v3 - __uint_as_float(ah[mt][3]));
            }
            uint32_t bh[4][2], bl[4][2];
#pragma unroll
            for (int nt = 0; nt < 4; nt++) {
                int n = wc * 32 + nt * 8 + gid;
                float w0 = Bs[buf][ks + tg    ][n];
                float w1 = Bs[buf][ks + tg + 4][n];
                bh[nt][0] = f2tf32(w0); bl[nt][0] = f2tf32(w0 - __uint_as_float(bh[nt][0]));
                bh[nt][1] = f2tf32(w1); bl[nt][1] = f2tf32(w1 - __uint_as_float(bh[nt][1]));
            }
#pragma unroll
            for (int mt = 0; mt < 4; mt++)
#pragma unroll
                for (int nt = 0; nt < 4; nt++) {
                    mma_tf32(acc[mt][nt], al[mt], bh[nt]);
                    mma_tf32(acc[mt][nt], ah[mt], bl[nt]);
                    mma_tf32(acc[mt][nt], ah[mt], bh[nt]);
                }
        }
        __syncthreads();
    }

#pragma unroll
    for (int mt = 0; mt < 4; mt++) {
        int rm = m0 + wr * 64 + mt * 16 + gid;
#pragma unroll
        for (int nt = 0; nt < 4; nt++) {
            int cn = n0 + wc * 32 + nt * 8 + 2 * tg;
#pragma unroll
            for (int half = 0; half < 2; half++) {
                int r = rm + half * 8;
                if (r >= M) continue;
                if (cn < Nc)     C[(size_t)r * Nc + cn]     = acc[mt][nt][half * 2 + 0];
                if (cn + 1 < Nc) C[(size_t)r * Nc + cn + 1] = acc[mt][nt][half * 2 + 1];
            }
        }
    }
}

// ============================================================
// Generic tiled SGEMM (fp32): final MLP layer only
// ============================================================
template<bool BIAS, bool RELU>
__global__ __launch_bounds__(256)
void sgemm(const float* __restrict__ A, const float* __restrict__ B,
           const float* __restrict__ bias, float* __restrict__ C,
           int M, int K, int Nc)
{
    __shared__ float As[8][128];
    __shared__ float Bs[8][128];

    const int tid = threadIdx.x;
    const int m0 = blockIdx.y * 128;
    const int n0 = blockIdx.x * 128;

    const int a_row = tid >> 1;
    const int a_col = (tid & 1) * 4;
    const int b_row = tid >> 5;
    const int b_col = (tid & 31) * 4;

    const int ty = tid >> 4;
    const int tx = tid & 15;

    float acc[8][8];
#pragma unroll
    for (int i = 0; i < 8; i++)
#pragma unroll
        for (int j = 0; j < 8; j++) acc[i][j] = 0.f;

    for (int k0 = 0; k0 < K; k0 += 8) {
        float av[4];
        const int gm = m0 + a_row;
#pragma unroll
        for (int i = 0; i < 4; i++) {
            int gk = k0 + a_col + i;
            av[i] = (gm < M && gk < K) ? A[(size_t)gm * K + gk] : 0.f;
        }
#pragma unroll
        for (int i = 0; i < 4; i++) As[a_col + i][a_row] = av[i];

        float bv[4];
        const int gk = k0 + b_row;
#pragma unroll
        for (int i = 0; i < 4; i++) {
            int gn = n0 + b_col + i;
            bv[i] = (gk < K && gn < Nc) ? B[(size_t)gk * Nc + gn] : 0.f;
        }
        *(float4*)&Bs[b_row][b_col] = make_float4(bv[0], bv[1], bv[2], bv[3]);

        __syncthreads();

#pragma unroll
        for (int kk = 0; kk < 8; kk++) {
            float4 a0 = *(const float4*)&As[kk][ty * 8];
            float4 a1 = *(const float4*)&As[kk][ty * 8 + 4];
            float4 b0 = *(const float4*)&Bs[kk][tx * 8];
            float4 b1 = *(const float4*)&Bs[kk][tx * 8 + 4];
            float ar[8] = {a0.x, a0.y, a0.z, a0.w, a1.x, a1.y, a1.z, a1.w};
            float br[8] = {b0.x, b0.y, b0.z, b0.w, b1.x, b1.y, b1.z, b1.w};
#pragma unroll
            for (int i = 0; i < 8; i++)
#pragma unroll
                for (int j = 0; j < 8; j++)
                    acc[i][j] = fmaf(ar[i], br[j], acc[i][j]);
        }
        __syncthreads();
    }

#pragma unroll
    for (int i = 0; i < 8; i++) {
        int gm = m0 + ty * 8 + i;
        if (gm >= M) continue;
#pragma unroll
        for (int j = 0; j < 8; j++) {
            int gn = n0 + tx * 8 + j;
            if (gn >= Nc) continue;
            float v = acc[i][j];
            if (BIAS) v += bias[gn];
            if (RELU) v = v > 0.f ? v : 0.f;
            C[(size_t)gm * Nc + gn] = v;
        }
    }
}

// ============================================================
// Attention coefficients: a_src[n,h], a_dst[n,h] (warp per (n,h))
// ============================================================
__global__ void att_kernel(const float* __restrict__ h,
                           const float* __restrict__ att_s,
                           const float* __restrict__ att_d,
                           float* __restrict__ asrc, float* __restrict__ adst)
{
    int w = (blockIdx.x * blockDim.x + threadIdx.x) >> 5;
    if (w >= NN * HH) return;
    int lane = threadIdx.x & 31;
    int n = w / HH, hh = w % HH;
    const float* hp = h + (size_t)n * HIDC + hh * FF;
    const float* as = att_s + hh * FF;
    const float* ad = att_d + hh * FF;
    float s1 = 0.f, s2 = 0.f;
    for (int f = lane; f < FF; f += 32) {
        float v = hp[f];
        s1 += v * as[f];
        s2 += v * ad[f];
    }
#pragma unroll
    for (int o = 16; o; o >>= 1) {
        s1 += __shfl_down_sync(0xffffffffu, s1, o);
        s2 += __shfl_down_sync(0xffffffffu, s2, o);
    }
    if (!lane) { asrc[w] = s1; adst[w] = s2; }
}

// ============================================================
// Graph structure kernels
// ============================================================
__global__ void zero_int(int* p, int n)
{
    int i = blockIdx.x * blockDim.x + threadIdx.x;
    if (i < n) p[i] = 0;
}

__global__ void copy_int(const int* __restrict__ a, int* __restrict__ b, int n)
{
    int i = blockIdx.x * blockDim.x + threadIdx.x;
    if (i < n) b[i] = a[i];
}

__global__ void hist_deg(const int* __restrict__ ei, int* __restrict__ deg)
{
    int e = blockIdx.x * blockDim.x + threadIdx.x;
    if (e >= ET) return;
    int d = (e < EE) ? ei[EE + e] : (e - EE);
    atomicAdd(&deg[d], 1);
}

__global__ void hist_batch(const int* __restrict__ batch, int* __restrict__ cnt)
{
    int i = blockIdx.x * blockDim.x + threadIdx.x;
    if (i < NN) atomicAdd(&cnt[batch[i]], 1);
}

// single-block exclusive scan, out has n+1 entries (out[n] = total)
__global__ void scan_excl(const int* __restrict__ in, int* __restrict__ out, int n)
{
    __shared__ int sh[1024];
    __shared__ int carry;
    if (threadIdx.x == 0) carry = 0;
    __syncthreads();
    for (int base = 0; base < n; base += 1024) {
        int i = base + threadIdx.x;
        int v = (i < n) ? in[i] : 0;
        sh[threadIdx.x] = v;
        __syncthreads();
        for (int off = 1; off < 1024; off <<= 1) {
            int t = (threadIdx.x >= off) ? sh[threadIdx.x - off] : 0;
            __syncthreads();
            sh[threadIdx.x] += t;
            __syncthreads();
        }
        int c0 = carry;
        if (i < n) out[i] = c0 + sh[threadIdx.x] - v;
        __syncthreads();
        if (threadIdx.x == 0) carry = c0 + sh[1023];
        __syncthreads();
    }
    if (threadIdx.x == 0) out[n] = carry;
}

__global__ void scatter_csr(const int* __restrict__ ei, int* __restrict__ wptr,
                            int* __restrict__ csrc)
{
    int e = blockIdx.x * blockDim.x + threadIdx.x;
    if (e >= ET) return;
    int s = (e < EE) ? ei[e] : (e - EE);
    int d = (e < EE) ? ei[EE + e] : (e - EE);
    int pos = atomicAdd(&wptr[d], 1);
    csrc[pos] = s;
}

__global__ void dinv_kernel(const int* __restrict__ deg, float* __restrict__ dinv)
{
    int i = blockIdx.x * blockDim.x + threadIdx.x;
    if (i < NN) dinv[i] = rsqrtf(fmaxf((float)deg[i], 1.f));
}

// ============================================================
// GAT softmax-aggregate: warp per destination node, 2-edge unroll.
// Lanes 0..9 handle even edge's heads, lanes 16..25 the odd edge's.
// ============================================================
__global__ __launch_bounds__(256)
void gat_agg(const float* __restrict__ h, const float* __restrict__ asrc,
             const float* __restrict__ adst, const int* __restrict__ rowptr,
             const int* __restrict__ csrc, const float* __restrict__ bgat,
             float* __restrict__ out1)
{
    __shared__ float wsh[8][2][HH];
    int warp = (blockIdx.x * 256 + threadIdx.x) >> 5;
    if (warp >= NN) return;
    int lane = threadIdx.x & 31;
    int wls = threadIdx.x >> 5;
    int d = warp;
    int jb = rowptr[d], je = rowptr[d + 1];

    int lh = lane & 15;
    bool act = lh < HH;
    float adv = act ? adst[d * HH + lh] : 0.f;

    // pass 1: softmax denominator per head (split across half-warps)
    float denom = 0.f;
    int j = jb;
    for (; j + 1 < je; j += 2) {
        if (act) {
            int s = csrc[(lane < 16) ? j : j + 1];
            float ev = asrc[s * HH + lh] + adv;
            ev = ev > 0.f ? ev : 0.2f * ev;
            denom += __expf(ev);
        }
    }
    if (j < je && lane < HH) {
        int s = csrc[j];
        float ev = asrc[s * HH + lh] + adv;
        ev = ev > 0.f ? ev : 0.2f * ev;
        denom += __expf(ev);
    }
    denom += __shfl_down_sync(0xffffffffu, denom, 16);
    float dh = __shfl_sync(0xffffffffu, denom, lh);   // combined denom for head lh
    float inv_d = 1.f / dh;

    // per-component head indices for this lane's float4 slots
    int4 hd4[7];
#pragma unroll
    for (int k = 0; k < 7; k++) {
        int t = lane + k * 32;
        int e0 = 4 * ((t < H4) ? t : 0);
        hd4[k] = make_int4(e0 / FF, (e0 + 1) / FF, (e0 + 2) / FF, (e0 + 3) / FF);
    }

    float4 acc[7];
#pragma unroll
    for (int k = 0; k < 7; k++) acc[k] = make_float4(0.f, 0.f, 0.f, 0.f);

    float (*myw)[HH] = wsh[wls];

    // pass 2: weighted aggregate, 2 edges at a time
    j = jb;
    for (; j + 1 < je; j += 2) {
        int s0 = csrc[j], s1 = csrc[j + 1];
        if (act) {
            int s = (lane < 16) ? s0 : s1;
            float ev = asrc[s * HH + lh] + adv;
            ev = ev > 0.f ? ev : 0.2f * ev;
            myw[lane >> 4][lh] = __expf(ev) * inv_d;
        }
        __syncwarp();
        const float4* hp0 = (const float4*)(h + (size_t)s0 * HIDC);
        const float4* hp1 = (const float4*)(h + (size_t)s1 * HIDC);
#pragma unroll
        for (int k = 0; k < 7; k++) {
            int t = lane + k * 32;
            if (t < H4) {
                float4 v0 = hp0[t];
                float4 v1 = hp1[t];
                acc[k].x = fmaf(myw[0][hd4[k].x], v0.x, fmaf(myw[1][hd4[k].x], v1.x, acc[k].x));
                acc[k].y = fmaf(myw[0][hd4[k].y], v0.y, fmaf(myw[1][hd4[k].y], v1.y, acc[k].y));
                acc[k].z = fmaf(myw[0][hd4[k].z], v0.z, fmaf(myw[1][hd4[k].z], v1.z, acc[k].z));
                acc[k].w = fmaf(myw[0][hd4[k].w], v0.w, fmaf(myw[1][hd4[k].w], v1.w, acc[k].w));
            }
        }
        __syncwarp();
    }
    if (j < je) {                       // tail edge
        int s0 = csrc[j];
        if (lane < HH) {
            float ev = asrc[s0 * HH + lh] + adv;
            ev = ev > 0.f ? ev : 0.2f * ev;
            myw[0][lh] = __expf(ev) * inv_d;
        }
        __syncwarp();
        const float4* hp0 = (const float4*)(h + (size_t)s0 * HIDC);
#pragma unroll
        for (int k = 0; k < 7; k++) {
            int t = lane + k * 32;
            if (t < H4) {
                float4 v0 = hp0[t];
                acc[k].x = fmaf(myw[0][hd4[k].x], v0.x, acc[k].x);
                acc[k].y = fmaf(myw[0][hd4[k].y], v0.y, acc[k].y);
                acc[k].z = fmaf(myw[0][hd4[k].z], v0.z, acc[k].z);
                acc[k].w = fmaf(myw[0][hd4[k].w], v0.w, acc[k].w);
            }
        }
        __syncwarp();
    }

    float4* op = (float4*)(out1 + (size_t)d * HIDC);
    const float4* bp = (const float4*)bgat;
#pragma unroll
    for (int k = 0; k < 7; k++) {
        int t = lane + k * 32;
        if (t < H4) {
            float4 b = bp[t];
            float4 v;
            v.x = fmaxf(acc[k].x + b.x, 0.f);
            v.y = fmaxf(acc[k].y + b.y, 0.f);
            v.z = fmaxf(acc[k].z + b.z, 0.f);
            v.w = fmaxf(acc[k].w + b.w, 0.f);
            op[t] = v;
        }
    }
}

// ============================================================
// GCN normalized aggregate: warp per destination node, 2-edge unroll.
// ============================================================
__global__ __launch_bounds__(256)
void gcn_agg(const float* __restrict__ h2, const float* __restrict__ dinv,
             const int* __restrict__ rowptr, const int* __restrict__ csrc,
             const float* __restrict__ bgcn, float* __restrict__ out2)
{
    int warp = (blockIdx.x * 256 + threadIdx.x) >> 5;
    if (warp >= NN) return;
    int lane = threadIdx.x & 31;
    int d = warp;
    int jb = rowptr[d], je = rowptr[d + 1];
    float dd = dinv[d];

    float4 acc[7];
#pragma unroll
    for (int k = 0; k < 7; k++) acc[k] = make_float4(0.f, 0.f, 0.f, 0.f);

    int j = jb;
    for (; j + 1 < je; j += 2) {
        int s0 = csrc[j], s1 = csrc[j + 1];
        float w0 = dinv[s0] * dd;
        float w1 = dinv[s1] * dd;
        const float4* hp0 = (const float4*)(h2 + (size_t)s0 * HIDC);
        const float4* hp1 = (const float4*)(h2 + (size_t)s1 * HIDC);
#pragma unroll
        for (int k = 0; k < 7; k++) {
            int t = lane + k * 32;
            if (t < H4) {
                float4 v0 = hp0[t];
                float4 v1 = hp1[t];
                acc[k].x = fmaf(w0, v0.x, fmaf(w1, v1.x, acc[k].x));
                acc[k].y = fmaf(w0, v0.y, fmaf(w1, v1.y, acc[k].y));
                acc[k].z = fmaf(w0, v0.z, fmaf(w1, v1.z, acc[k].z));
                acc[k].w = fmaf(w0, v0.w, fmaf(w1, v1.w, acc[k].w));
            }
        }
    }
    if (j < je) {
        int s0 = csrc[j];
        float w0 = dinv[s0] * dd;
        const float4* hp0 = (const float4*)(h2 + (size_t)s0 * HIDC);
#pragma unroll
        for (int k = 0; k < 7; k++) {
            int t = lane + k * 32;
            if (t < H4) {
                float4 v0 = hp0[t];
                acc[k].x = fmaf(w0, v0.x, acc[k].x);
                acc[k].y = fmaf(w0, v0.y, acc[k].y);
                acc[k].z = fmaf(w0, v0.z, acc[k].z);
                acc[k].w = fmaf(w0, v0.w, acc[k].w);
            }
        }
    }

    float4* op = (float4*)(out2 + (size_t)d * HIDC);
    const float4* bp = (const float4*)bgcn;
#pragma unroll
    for (int k = 0; k < 7; k++) {
        int t = lane + k * 32;
        if (t < H4) {
            float4 b = bp[t];
            float4 v;
            v.x = fmaxf(acc[k].x + b.x, 0.f);
            v.y = fmaxf(acc[k].y + b.y, 0.f);
            v.z = fmaxf(acc[k].z + b.z, 0.f);
            v.w = fmaxf(acc[k].w + b.w, 0.f);
            op[t] = v;
        }
    }
}

// ============================================================
// Global mean/max pool, block per graph (batch is sorted), float4
// ============================================================
__global__ __launch_bounds__(256)
void pool_kernel(const float* __restrict__ out2, const int* __restrict__ gstart,
                 float* __restrict__ pooled)
{
    int g = blockIdx.x;
    int t = threadIdx.x;          // one float4 slot per thread (195 < 256)
    int start = gstart[g];
    int cnt = gstart[g + 1] - start;

    if (t >= H4) return;

    float4 s = make_float4(0.f, 0.f, 0.f, 0.f);
    float4 mx = make_float4(-INFINITY, -INFINITY, -INFINITY, -INFINITY);

    for (int i = 0; i < cnt; i++) {
        const float4* p = (const float4*)(out2 + (size_t)(start + i) * HIDC);
        float4 v = p[t];
        s.x += v.x; s.y += v.y; s.z += v.z; s.w += v.w;
        mx.x = fmaxf(mx.x, v.x); mx.y = fmaxf(mx.y, v.y);
        mx.z = fmaxf(mx.z, v.z); mx.w = fmaxf(mx.w, v.w);
    }
    float inv = 1.f / fmaxf((float)cnt, 1.f);
    float4 mean = make_float4(s.x * inv, s.y * inv, s.z * inv, s.w * inv);
    if (cnt <= 0) mx = make_float4(0.f, 0.f, 0.f, 0.f);

    float4* pm = (float4*)(pooled + (size_t)g * PO);
    float4* px = (float4*)(pooled + (size_t)g * PO + HIDC);
    pm[t] = mean;
    px[t] = mx;
}

// ============================================================
// Launch
// ============================================================
extern "C" void kernel_launch(void* const* d_in, const int* in_sizes, int n_in,
                              void* d_out, int out_size)
{
    const float* x     = (const float*)d_in[0];
    const int*   ei    = (const int*)  d_in[1];
    const int*   batch = (const int*)  d_in[2];
    const float* Wgat  = (const float*)d_in[3];
    const float* att_s = (const float*)d_in[4];
    const float* att_d = (const float*)d_in[5];
    const float* bgat  = (const float*)d_in[6];
    const float* Wgcn  = (const float*)d_in[7];
    const float* bgcn  = (const float*)d_in[8];
    const float* W1    = (const float*)d_in[9];
    const float* b1    = (const float*)d_in[10];
    const float* W2    = (const float*)d_in[11];
    const float* b2    = (const float*)d_in[12];
    float* out = (float*)d_out;

    float* base = nullptr;
    cudaGetSymbolAddress((void**)&base, g_buf);

    float* ph     = base + OFF_H;
    float* pout1  = base + OFF_OUT1;
    float* ph2    = base + OFF_H2;
    float* pout2  = base + OFF_OUT2;
    float* pasrc  = base + OFF_ASRC;
    float* padst  = base + OFF_ADST;
    float* pdinv  = base + OFF_DINV;
    float* ppool  = base + OFF_POOL;
    float* pfc1   = base + OFF_FC1;
    int*   pdeg   = (int*)(base + OFF_DEG);
    int*   prowp  = (int*)(base + OFF_ROWP);
    int*   pwptr  = (int*)(base + OFF_WPTR);
    int*   pcsrc  = (int*)(base + OFF_CSRC);
    int*   pcnt   = (int*)(base + OFF_CNT);
    int*   pgst   = (int*)(base + OFF_GST);

    // 1. h = x @ W_gat   [N, 780]  (split-TF32: fp32 accuracy on tensor pipe)
    {
        dim3 grid((HIDC + 127) / 128, (NN + 127) / 128);
        tf32_gemm_split<<<grid, 256>>>(x, Wgat, ph, NN, FF, HIDC);
    }

    // 2. attention coefficients
    {
        int warps = NN * HH;
        int blocks = (warps * 32 + 255) / 256;
        att_kernel<<<blocks, 256>>>(ph, att_s, att_d, pasrc, padst);
    }

    // 3. CSR build + dinv
    zero_int<<<(NN + 255) / 256, 256>>>(pdeg, NN);
    hist_deg<<<(ET + 255) / 256, 256>>>(ei, pdeg);
    scan_excl<<<1, 1024>>>(pdeg, prowp, NN);
    copy_int<<<(NN + 255) / 256, 256>>>(prowp, pwptr, NN);
    scatter_csr<<<(ET + 255) / 256, 256>>>(ei, pwptr, pcsrc);
    dinv_kernel<<<(NN + 255) / 256, 256>>>(pdeg, pdinv);

    // 4. GAT softmax-aggregate + bias + relu
    gat_agg<<<(NN * 32 + 255) / 256, 256>>>(ph, pasrc, padst, prowp, pcsrc, bgat, pout1);

    // 5. h2 = out1 @ W_gcn   [N, 780]  (pipelined TF32 — dominant GEMM)
    {
        dim3 grid((HIDC + 127) / 128, (NN + 127) / 128);
        tf32_gemm_pipe<false, false><<<grid, 256>>>(pout1, Wgcn, nullptr, ph2, NN, HIDC, HIDC);
    }

    // 6. GCN aggregate + bias + relu
    gcn_agg<<<(NN * 32 + 255) / 256, 256>>>(ph2, pdinv, prowp, pcsrc, bgcn, pout2);

    // 7. graph node ranges (batch is sorted)
    zero_int<<<(GG + 255) / 256, 256>>>(pcnt, GG);
    hist_batch<<<(NN + 255) / 256, 256>>>(batch, pcnt);
    scan_excl<<<1, 1024>>>(pcnt, pgst, GG);

    // 8. mean/max pooling
    pool_kernel<<<GG, 256>>>(pout2, pgst, ppool);

    // 9. fc1 = relu(pooled @ W1 + b1)   (pipelined TF32)
    {
        dim3 grid((P1 + 127) / 128, (GG + 127) / 128);
        tf32_gemm_pipe<true, true><<<grid, 256>>>(ppool, W1, b1, pfc1, GG, PO, P1);
    }

    // 10. out = fc1 @ W2 + b2  (fp32: final layer, small)
    {
        dim3 grid((OC + 127) / 128, (GG + 127) / 128);
        sgemm<true, false><<<grid, 256>>>(pfc1, W2, b2, out, GG, P1, OC);
    }
}

// round 13
// speedup vs baseline: 1.5020x; 1.5020x over previous
#include <cuda_runtime.h>
#include <math.h>
#include <stdint.h>

// Problem constants
constexpr int NN   = 30000;      // nodes
constexpr int EE   = 240000;     // edges (before self loops)
constexpr int GG   = 1000;       // graphs
constexpr int FF   = 78;         // in features
constexpr int FP   = 80;         // padded in features (16B-aligned rows)
constexpr int HH   = 10;         // GAT heads
constexpr int HIDC = 780;        // F*H
constexpr int ET   = EE + NN;    // edges with self loops
constexpr int P1   = 1500;       // fc1 width
constexpr int PO   = 2 * HIDC;   // pooled width 1560
constexpr int OC   = 128;        // output classes
constexpr int H4   = HIDC / 4;   // 195 float4 per feature row

// ---- one big device scratch buffer (no allocations allowed) ----
// Every offset aligned up to 4 floats (16 B) so float4 / cp.async.16 are safe.
constexpr size_t A4(size_t x) { return (x + 3) & ~(size_t)3; }

constexpr size_t OFF_H    = 0;
constexpr size_t OFF_OUT1 = A4(OFF_H    + (size_t)NN * HIDC);
constexpr size_t OFF_H2   = A4(OFF_OUT1 + (size_t)NN * HIDC);
constexpr size_t OFF_OUT2 = A4(OFF_H2   + (size_t)NN * HIDC);
constexpr size_t OFF_ASRC = A4(OFF_OUT2 + (size_t)NN * HIDC);
constexpr size_t OFF_ADST = A4(OFF_ASRC + (size_t)NN * HH);
constexpr size_t OFF_DINV = A4(OFF_ADST + (size_t)NN * HH);
constexpr size_t OFF_POOL = A4(OFF_DINV + NN);
constexpr size_t OFF_FC1  = A4(OFF_POOL + (size_t)GG * PO);
constexpr size_t OFF_DEG  = A4(OFF_FC1  + (size_t)GG * P1);
constexpr size_t OFF_ROWP = A4(OFF_DEG  + NN);
constexpr size_t OFF_WPTR = A4(OFF_ROWP + NN + 1);
constexpr size_t OFF_CSRC = A4(OFF_WPTR + NN);
constexpr size_t OFF_CNT  = A4(OFF_CSRC + ET);
constexpr size_t OFF_GST  = A4(OFF_CNT  + GG);
constexpr size_t OFF_MS   = A4(OFF_GST  + GG + 1);       // M_src [78*10]
constexpr size_t OFF_MD   = A4(OFF_MS   + FF * HH);      // M_dst [78*10]
constexpr size_t OFF_XP   = A4(OFF_MD   + FF * HH);      // x padded [NN*80]
constexpr size_t OFF_WP   = A4(OFF_XP   + (size_t)NN * FP);  // Wgat padded [80*780]
constexpr size_t TOTALF   = OFF_WP   + (size_t)FP * HIDC;

static_assert(OFF_XP % 4 == 0 && OFF_WP % 4 == 0, "16B alignment");

__device__ __align__(16) float g_buf[TOTALF];

// ============================================================
// helpers
// ============================================================
__device__ __forceinline__ uint32_t f2tf32(float v)
{
    uint32_t r;
    asm("cvt.rna.tf32.f32 %0, %1;" : "=r"(r) : "f"(v));
    return r;
}

__device__ __forceinline__ void mma_tf32(float c[4],
                                         const uint32_t a[4],
                                         const uint32_t b[2])
{
    asm volatile(
        "mma.sync.aligned.m16n8k8.row.col.f32.tf32.tf32.f32 "
        "{%0,%1,%2,%3}, {%4,%5,%6,%7}, {%8,%9}, {%0,%1,%2,%3};"
        : "+f"(c[0]), "+f"(c[1]), "+f"(c[2]), "+f"(c[3])
        : "r"(a[0]), "r"(a[1]), "r"(a[2]), "r"(a[3]),
          "r"(b[0]), "r"(b[1]));
}

__device__ __forceinline__ void cp_async16(void* smem_dst, const void* gsrc, int nbytes)
{
    uint32_t d = (uint32_t)__cvta_generic_to_shared(smem_dst);
    asm volatile("cp.async.cg.shared.global [%0], [%1], 16, %2;"
                 :: "r"(d), "l"(gsrc), "r"(nbytes));
}
__device__ __forceinline__ void cp_commit() { asm volatile("cp.async.commit_group;"); }
template<int N> __device__ __forceinline__ void cp_wait()
{ asm volatile("cp.async.wait_group %0;" :: "n"(N)); }

// ============================================================
// Pipelined TF32 GEMM: C[M,Nc] = A[M,K] @ B[K,Nc] (+bias)(+relu)
// 128x128 block tile, BK=16, double-buffered cp.async, 256 thr.
// REQUIRES: K % 4 == 0, Nc % 4 == 0, A and B 16B-aligned.
// Call sites: K in {80, 780, 1560} — all satisfy this.
// ============================================================
template<bool BIAS, bool RELU>
__global__ __launch_bounds__(256, 2)
void tf32_gemm_pipe(const float* __restrict__ A, const float* __restrict__ B,
                    const float* __restrict__ bias, float* __restrict__ C,
                    int M, int K, int Nc)
{
    __shared__ __align__(16) float As[2][128][20];
    __shared__ __align__(16) float Bs[2][16][136];

    const int tid  = threadIdx.x;
    const int warp = tid >> 5, lane = tid & 31;
    const int gid  = lane >> 2, tg = lane & 3;
    const int wr   = warp >> 2, wc = warp & 3;        // 2 x 4 warp grid
    const int m0   = blockIdx.y * 128, n0 = blockIdx.x * 128;

    const int a_row = tid >> 1;            // 0..127
    const int a_c0  = (tid & 1) * 8;       // 0 or 8
    const int b_r   = tid >> 4;            // 0..15
    const int b_c0  = (tid & 15) * 8;      // 0..120

    const int gmA = m0 + a_row;
    const float* a_base = A + (size_t)(gmA < M ? gmA : M - 1) * K;
    const bool a_rowok = (gmA < M);

    float acc[4][4][4];
#pragma unroll
    for (int i = 0; i < 4; i++)
#pragma unroll
        for (int j = 0; j < 4; j++)
#pragma unroll
            for (int k = 0; k < 4; k++) acc[i][j][k] = 0.f;

    const int nk = (K + 15) / 16;

    auto load_tile = [&](int buf, int k0) {
#pragma unroll
        for (int ch = 0; ch < 2; ch++) {
            int c = a_c0 + ch * 4;
            int gk = k0 + c;
            bool ok = a_rowok && (gk + 4 <= K);     // K%4==0: full-or-none
            const float* src = a_base + (gk + 4 <= K ? gk : 0);
            cp_async16(&As[buf][a_row][c], src, ok ? 16 : 0);
        }
        int gkB = k0 + b_r;
        const float* b_base = B + (size_t)(gkB < K ? gkB : K - 1) * Nc;
#pragma unroll
        for (int ch = 0; ch < 2; ch++) {
            int c = b_c0 + ch * 4;
            int gn = n0 + c;
            bool ok = (gkB < K) && (gn + 4 <= Nc);
            const float* src = b_base + (gn + 4 <= Nc ? gn : 0);
            cp_async16(&Bs[buf][b_r][c], src, ok ? 16 : 0);
        }
    };

    load_tile(0, 0);
    cp_commit();

    for (int t = 0; t < nk; t++) {
        int buf = t & 1;
        if (t + 1 < nk) load_tile(buf ^ 1, (t + 1) * 16);
        cp_commit();
        cp_wait<1>();
        __syncthreads();

#pragma unroll
        for (int ks = 0; ks < 16; ks += 8) {
            uint32_t af[4][4];
#pragma unroll
            for (int mt = 0; mt < 4; mt++) {
                int m = wr * 64 + mt * 16;
                af[mt][0] = f2tf32(As[buf][m + gid    ][ks + tg    ]);
                af[mt][1] = f2tf32(As[buf][m + gid + 8][ks + tg    ]);
                af[mt][2] = f2tf32(As[buf][m + gid    ][ks + tg + 4]);
                af[mt][3] = f2tf32(As[buf][m + gid + 8][ks + tg + 4]);
            }
            uint32_t bf[4][2];
#pragma unroll
            for (int nt = 0; nt < 4; nt++) {
                int n = wc * 32 + nt * 8 + gid;
                bf[nt][0] = f2tf32(Bs[buf][ks + tg    ][n]);
                bf[nt][1] = f2tf32(Bs[buf][ks + tg + 4][n]);
            }
#pragma unroll
            for (int mt = 0; mt < 4; mt++)
#pragma unroll
                for (int nt = 0; nt < 4; nt++)
                    mma_tf32(acc[mt][nt], af[mt], bf[nt]);
        }
        __syncthreads();
    }

#pragma unroll
    for (int mt = 0; mt < 4; mt++) {
        int rm = m0 + wr * 64 + mt * 16 + gid;
#pragma unroll
        for (int nt = 0; nt < 4; nt++) {
            int cn = n0 + wc * 32 + nt * 8 + 2 * tg;
#pragma unroll
            for (int half = 0; half < 2; half++) {
                int r = rm + half * 8;
                if (r >= M) continue;
                float v0 = acc[mt][nt][half * 2 + 0];
                float v1 = acc[mt][nt][half * 2 + 1];
                if (cn < Nc) {
                    float v = v0;
                    if (BIAS) v += bias[cn];
                    if (RELU) v = v > 0.f ? v : 0.f;
                    C[(size_t)r * Nc + cn] = v;
                }
                if (cn + 1 < Nc) {
                    float v = v1;
                    if (BIAS) v += bias[cn + 1];
                    if (RELU) v = v > 0.f ? v : 0.f;
                    C[(size_t)r * Nc + cn + 1] = v;
                }
            }
        }
    }
}

// ============================================================
// Generic tiled SGEMM (fp32): final MLP layer only
// ============================================================
template<bool BIAS, bool RELU>
__global__ __launch_bounds__(256)
void sgemm(const float* __restrict__ A, const float* __restrict__ B,
           const float* __restrict__ bias, float* __restrict__ C,
           int M, int K, int Nc)
{
    __shared__ float As[8][128];
    __shared__ float Bs[8][128];

    const int tid = threadIdx.x;
    const int m0 = blockIdx.y * 128;
    const int n0 = blockIdx.x * 128;

    const int a_row = tid >> 1;
    const int a_col = (tid & 1) * 4;
    const int b_row = tid >> 5;
    const int b_col = (tid & 31) * 4;

    const int ty = tid >> 4;
    const int tx = tid & 15;

    float acc[8][8];
#pragma unroll
    for (int i = 0; i < 8; i++)
#pragma unroll
        for (int j = 0; j < 8; j++) acc[i][j] = 0.f;

    for (int k0 = 0; k0 < K; k0 += 8) {
        float av[4];
        const int gm = m0 + a_row;
#pragma unroll
        for (int i = 0; i < 4; i++) {
            int gk = k0 + a_col + i;
            av[i] = (gm < M && gk < K) ? A[(size_t)gm * K + gk] : 0.f;
        }
#pragma unroll
        for (int i = 0; i < 4; i++) As[a_col + i][a_row] = av[i];

        float bv[4];
        const int gk = k0 + b_row;
#pragma unroll
        for (int i = 0; i < 4; i++) {
            int gn = n0 + b_col + i;
            bv[i] = (gk < K && gn < Nc) ? B[(size_t)gk * Nc + gn] : 0.f;
        }
        *(float4*)&Bs[b_row][b_col] = make_float4(bv[0], bv[1], bv[2], bv[3]);

        __syncthreads();

#pragma unroll
        for (int kk = 0; kk < 8; kk++) {
            float4 a0 = *(const float4*)&As[kk][ty * 8];
            float4 a1 = *(const float4*)&As[kk][ty * 8 + 4];
            float4 b0 = *(const float4*)&Bs[kk][tx * 8];
            float4 b1 = *(const float4*)&Bs[kk][tx * 8 + 4];
            float ar[8] = {a0.x, a0.y, a0.z, a0.w, a1.x, a1.y, a1.z, a1.w};
            float br[8] = {b0.x, b0.y, b0.z, b0.w, b1.x, b1.y, b1.z, b1.w};
#pragma unroll
            for (int i = 0; i < 8; i++)
#pragma unroll
                for (int j = 0; j < 8; j++)
                    acc[i][j] = fmaf(ar[i], br[j], acc[i][j]);
        }
        __syncthreads();
    }

#pragma unroll
    for (int i = 0; i < 8; i++) {
        int gm = m0 + ty * 8 + i;
        if (gm >= M) continue;
#pragma unroll
        for (int j = 0; j < 8; j++) {
            int gn = n0 + tx * 8 + j;
            if (gn >= Nc) continue;
            float v = acc[i][j];
            if (BIAS) v += bias[gn];
            if (RELU) v = v > 0.f ? v : 0.f;
            C[(size_t)gm * Nc + gn] = v;
        }
    }
}

// ============================================================
// Pad x [NN,78] -> x_pad [NN,80] (cols 78,79 = 0)
// ============================================================
__global__ __launch_bounds__(256)
void pad_x(const float* __restrict__ x, float* __restrict__ xp)
{
    int i = blockIdx.x * 256 + threadIdx.x;
    if (i >= NN * FP) return;
    int row = i / FP, col = i % FP;
    xp[i] = (col < FF) ? x[(size_t)row * FF + col] : 0.f;
}

// ============================================================
// Pad Wgat [78,780] -> W_pad [80,780] (rows 78,79 = 0)
// ============================================================
__global__ __launch_bounds__(256)
void pad_w(const float* __restrict__ w, float* __restrict__ wp)
{
    int i = blockIdx.x * 256 + threadIdx.x;
    if (i >= FP * HIDC) return;
    int row = i / HIDC;
    wp[i] = (row < FF) ? w[i] : 0.f;
}

// ============================================================
// Fold attention vectors into W_gat (256 thr/block):
// M_src[f*HH + h] = sum_f' W_gat[f, h*FF+f'] * att_src[h, f']
// ============================================================
__global__ __launch_bounds__(256)
void fold_att(const float* __restrict__ Wgat,
              const float* __restrict__ att_s,
              const float* __restrict__ att_d,
              float* __restrict__ Ms, float* __restrict__ Md)
{
    int t = blockIdx.x * 256 + threadIdx.x;
    if (t >= FF * HH) return;
    int f = t / HH, h = t % HH;
    const float* wrow = Wgat + (size_t)f * HIDC + h * FF;
    const float* as = att_s + h * FF;
    const float* ad = att_d + h * FF;
    float s1 = 0.f, s2 = 0.f;
    for (int f2 = 0; f2 < FF; f2++) {
        float w = wrow[f2];
        s1 += w * as[f2];
        s2 += w * ad[f2];
    }
    Ms[f * HH + h] = s1;
    Md[f * HH + h] = s2;
}

// ============================================================
// Attention coefficients directly from x (fp32 exact):
// a_src[n,h] = sum_f x[n,f] * M_src[f,h]; same for dst.
// Block: 320 threads = 32 nodes x 10 heads.
// ============================================================
__global__ __launch_bounds__(320)
void att_direct(const float* __restrict__ x,
                const float* __restrict__ Ms, const float* __restrict__ Md,
                float* __restrict__ asrc, float* __restrict__ adst)
{
    __shared__ float sMs[FF * HH];
    __shared__ float sMd[FF * HH];
    int tid = threadIdx.x;
    for (int i = tid; i < FF * HH; i += 320) {
        sMs[i] = Ms[i];
        sMd[i] = Md[i];
    }
    __syncthreads();

    int n = blockIdx.x * 32 + tid / HH;
    int h = tid % HH;
    if (n >= NN) return;

    const float* xp = x + (size_t)n * FF;
    float s1 = 0.f, s2 = 0.f;
#pragma unroll 6
    for (int f = 0; f < FF; f++) {
        float xv = xp[f];                 // broadcast across the 10 heads
        s1 = fmaf(xv, sMs[f * HH + h], s1);
        s2 = fmaf(xv, sMd[f * HH + h], s2);
    }
    asrc[n * HH + h] = s1;
    adst[n * HH + h] = s2;
}

// ============================================================
// Graph structure kernels
// ============================================================
__global__ __launch_bounds__(256)
void zero_int(int* p, int n)
{
    int i = blockIdx.x * blockDim.x + threadIdx.x;
    if (i < n) p[i] = 0;
}

__global__ __launch_bounds__(256)
void copy_int(const int* __restrict__ a, int* __restrict__ b, int n)
{
    int i = blockIdx.x * blockDim.x + threadIdx.x;
    if (i < n) b[i] = a[i];
}

__global__ __launch_bounds__(256)
void hist_deg(const int* __restrict__ ei, int* __restrict__ deg)
{
    int e = blockIdx.x * blockDim.x + threadIdx.x;
    if (e >= ET) return;
    int d = (e < EE) ? ei[EE + e] : (e - EE);
    atomicAdd(&deg[d], 1);
}

__global__ __launch_bounds__(256)
void hist_batch(const int* __restrict__ batch, int* __restrict__ cnt)
{
    int i = blockIdx.x * blockDim.x + threadIdx.x;
    if (i < NN) atomicAdd(&cnt[batch[i]], 1);
}

// single-block exclusive scan, out has n+1 entries (out[n] = total)
__global__ __launch_bounds__(1024)
void scan_excl(const int* __restrict__ in, int* __restrict__ out, int n)
{
    __shared__ int sh[1024];
    __shared__ int carry;
    if (threadIdx.x == 0) carry = 0;
    __syncthreads();
    for (int base = 0; base < n; base += 1024) {
        int i = base + threadIdx.x;
        int v = (i < n) ? in[i] : 0;
        sh[threadIdx.x] = v;
        __syncthreads();
        for (int off = 1; off < 1024; off <<= 1) {
            int t = (threadIdx.x >= off) ? sh[threadIdx.x - off] : 0;
            __syncthreads();
            sh[threadIdx.x] += t;
            __syncthreads();
        }
        int c0 = carry;
        if (i < n) out[i] = c0 + sh[threadIdx.x] - v;
        __syncthreads();
        if (threadIdx.x == 0) carry = c0 + sh[1023];
        __syncthreads();
    }
    if (threadIdx.x == 0) out[n] = carry;
}

__global__ __launch_bounds__(256)
void scatter_csr(const int* __restrict__ ei, int* __restrict__ wptr,
                 int* __restrict__ csrc)
{
    int e = blockIdx.x * blockDim.x + threadIdx.x;
    if (e >= ET) return;
    int s = (e < EE) ? ei[e] : (e - EE);
    int d = (e < EE) ? ei[EE + e] : (e - EE);
    int pos = atomicAdd(&wptr[d], 1);
    csrc[pos] = s;
}

__global__ __launch_bounds__(256)
void dinv_kernel(const int* __restrict__ deg, float* __restrict__ dinv)
{
    int i = blockIdx.x * blockDim.x + threadIdx.x;
    if (i < NN) dinv[i] = rsqrtf(fmaxf((float)deg[i], 1.f));
}

// ============================================================
// GAT softmax-aggregate: warp per destination node. float4 path.
// ============================================================
__global__ __launch_bounds__(256)
void gat_agg(const float* __restrict__ h, const float* __restrict__ asrc,
             const float* __restrict__ adst, const int* __restrict__ rowptr,
             const int* __restrict__ csrc, const float* __restrict__ bgat,
             float* __restrict__ out1)
{
    __shared__ float wsh[8][HH];
    int warp = (blockIdx.x * 256 + threadIdx.x) >> 5;
    if (warp >= NN) return;
    int lane = threadIdx.x & 31;
    float* myw = wsh[(threadIdx.x >> 5)];
    int d = warp;
    int jb = rowptr[d], je = rowptr[d + 1];

    float ad = (lane < HH) ? adst[d * HH + lane] : 0.f;

    // pass 1: softmax denominator per head (lanes 0..9)
    float denom = 0.f;
    for (int j = jb; j < je; j++) {
        int s = csrc[j];
        if (lane < HH) {
            float ev = asrc[s * HH + lane] + ad;
            ev = ev > 0.f ? ev : 0.2f * ev;
            denom += __expf(ev);
        }
    }
    float inv_d = (lane < HH) ? 1.f / denom : 0.f;

    // per-component head indices for this lane's float4 slots
    int4 hd4[7];
#pragma unroll
    for (int k = 0; k < 7; k++) {
        int t = lane + k * 32;
        int e0 = 4 * ((t < H4) ? t : 0);
        hd4[k] = make_int4(e0 / FF, (e0 + 1) / FF, (e0 + 2) / FF, (e0 + 3) / FF);
    }

    float4 acc[7];
#pragma unroll
    for (int k = 0; k < 7; k++) acc[k] = make_float4(0.f, 0.f, 0.f, 0.f);

    // pass 2: weighted aggregate (float4 gathers)
    for (int j = jb; j < je; j++) {
        int s = csrc[j];
        if (lane < HH) {
            float ev = asrc[s * HH + lane] + ad;
            ev = ev > 0.f ? ev : 0.2f * ev;
            myw[lane] = __expf(ev) * inv_d;
        }
        __syncwarp();
        const float4* hp = (const float4*)(h + (size_t)s * HIDC);
#pragma unroll
        for (int k = 0; k < 7; k++) {
            int t = lane + k * 32;
            if (t < H4) {
                float4 v = hp[t];
                acc[k].x = fmaf(myw[hd4[k].x], v.x, acc[k].x);
                acc[k].y = fmaf(myw[hd4[k].y], v.y, acc[k].y);
                acc[k].z = fmaf(myw[hd4[k].z], v.z, acc[k].z);
                acc[k].w = fmaf(myw[hd4[k].w], v.w, acc[k].w);
            }
        }
        __syncwarp();
    }

    float4* op = (float4*)(out1 + (size_t)d * HIDC);
    const float4* bp = (const float4*)bgat;
#pragma unroll
    for (int k = 0; k < 7; k++) {
        int t = lane + k * 32;
        if (t < H4) {
            float4 b = bp[t];
            float4 v;
            v.x = fmaxf(acc[k].x + b.x, 0.f);
            v.y = fmaxf(acc[k].y + b.y, 0.f);
            v.z = fmaxf(acc[k].z + b.z, 0.f);
            v.w = fmaxf(acc[k].w + b.w, 0.f);
            op[t] = v;
        }
    }
}

// ============================================================
// GCN normalized aggregate: warp per destination node. float4.
// ============================================================
__global__ __launch_bounds__(256)
void gcn_agg(const float* __restrict__ h2, const float* __restrict__ dinv,
             const int* __restrict__ rowptr, const int* __restrict__ csrc,
             const float* __restrict__ bgcn, float* __restrict__ out2)
{
    int warp = (blockIdx.x * 256 + threadIdx.x) >> 5;
    if (warp >= NN) return;
    int lane = threadIdx.x & 31;
    int d = warp;
    int jb = rowptr[d], je = rowptr[d + 1];
    float dd = dinv[d];

    float4 acc[7];
#pragma unroll
    for (int k = 0; k < 7; k++) acc[k] = make_float4(0.f, 0.f, 0.f, 0.f);

    for (int j = jb; j < je; j++) {
        int s = csrc[j];
        float w = dinv[s] * dd;
        const float4* hp = (const float4*)(h2 + (size_t)s * HIDC);
#pragma unroll
        for (int k = 0; k < 7; k++) {
            int t = lane + k * 32;
            if (t < H4) {
                float4 v = hp[t];
                acc[k].x = fmaf(w, v.x, acc[k].x);
                acc[k].y = fmaf(w, v.y, acc[k].y);
                acc[k].z = fmaf(w, v.z, acc[k].z);
                acc[k].w = fmaf(w, v.w, acc[k].w);
            }
        }
    }

    float4* op = (float4*)(out2 + (size_t)d * HIDC);
    const float4* bp = (const float4*)bgcn;
#pragma unroll
    for (int k = 0; k < 7; k++) {
        int t = lane + k * 32;
        if (t < H4) {
            float4 b = bp[t];
            float4 v;
            v.x = fmaxf(acc[k].x + b.x, 0.f);
            v.y = fmaxf(acc[k].y + b.y, 0.f);
            v.z = fmaxf(acc[k].z + b.z, 0.f);
            v.w = fmaxf(acc[k].w + b.w, 0.f);
            op[t] = v;
        }
    }
}

// ============================================================
// Global mean/max pool, block per graph (batch is sorted), float4
// ============================================================
__global__ __launch_bounds__(256)
void pool_kernel(const float* __restrict__ out2, const int* __restrict__ gstart,
                 float* __restrict__ pooled)
{
    int g = blockIdx.x;
    int t = threadIdx.x;          // one float4 slot per thread (195 < 256)
    int start = gstart[g];
    int cnt = gstart[g + 1] - start;

    if (t >= H4) return;

    float4 s = make_float4(0.f, 0.f, 0.f, 0.f);
    float4 mx = make_float4(-INFINITY, -INFINITY, -INFINITY, -INFINITY);

    for (int i = 0; i < cnt; i++) {
        const float4* p = (const float4*)(out2 + (size_t)(start + i) * HIDC);
        float4 v = p[t];
        s.x += v.x; s.y += v.y; s.z += v.z; s.w += v.w;
        mx.x = fmaxf(mx.x, v.x); mx.y = fmaxf(mx.y, v.y);
        mx.z = fmaxf(mx.z, v.z); mx.w = fmaxf(mx.w, v.w);
    }
    float inv = 1.f / fmaxf((float)cnt, 1.f);
    float4 mean = make_float4(s.x * inv, s.y * inv, s.z * inv, s.w * inv);
    if (cnt <= 0) mx = make_float4(0.f, 0.f, 0.f, 0.f);

    float4* pm = (float4*)(pooled + (size_t)g * PO);
    float4* px = (float4*)(pooled + (size_t)g * PO + HIDC);
    pm[t] = mean;
    px[t] = mx;
}

// ============================================================
// Launch
// ============================================================
extern "C" void kernel_launch(void* const* d_in, const int* in_sizes, int n_in,
                              void* d_out, int out_size)
{
    const float* x     = (const float*)d_in[0];
    const int*   ei    = (const int*)  d_in[1];
    const int*   batch = (const int*)  d_in[2];
    const float* Wgat  = (const float*)d_in[3];
    const float* att_s = (const float*)d_in[4];
    const float* att_d = (const float*)d_in[5];
    const float* bgat  = (const float*)d_in[6];
    const float* Wgcn  = (const float*)d_in[7];
    const float* bgcn  = (const float*)d_in[8];
    const float* W1    = (const float*)d_in[9];
    const float* b1    = (const float*)d_in[10];
    const float* W2    = (const float*)d_in[11];
    const float* b2    = (const float*)d_in[12];
    float* out = (float*)d_out;

    float* base = nullptr;
    cudaGetSymbolAddress((void**)&base, g_buf);

    float* ph     = base + OFF_H;
    float* pout1  = base + OFF_OUT1;
    float* ph2    = base + OFF_H2;
    float* pout2  = base + OFF_OUT2;
    float* pasrc  = base + OFF_ASRC;
    float* padst  = base + OFF_ADST;
    float* pdinv  = base + OFF_DINV;
    float* ppool  = base + OFF_POOL;
    float* pfc1   = base + OFF_FC1;
    float* pms    = base + OFF_MS;
    float* pmd    = base + OFF_MD;
    float* pxp    = base + OFF_XP;
    float* pwp    = base + OFF_WP;
    int*   pdeg   = (int*)(base + OFF_DEG);
    int*   prowp  = (int*)(base + OFF_ROWP);
    int*   pwptr  = (int*)(base + OFF_WPTR);
    int*   pcsrc  = (int*)(base + OFF_CSRC);
    int*   pcnt   = (int*)(base + OFF_CNT);
    int*   pgst   = (int*)(base + OFF_GST);

    // 0. pad x -> [NN,80] and Wgat -> [80,780] for 16B-aligned cp.async
    pad_x<<<(NN * FP + 255) / 256, 256>>>(x, pxp);
    pad_w<<<(FP * HIDC + 255) / 256, 256>>>(Wgat, pwp);

    // 1a. fold attention vectors: M_src/M_dst [78,10]  (fp32 exact, tiny)
    fold_att<<<(FF * HH + 255) / 256, 256>>>(Wgat, att_s, att_d, pms, pmd);

    // 1b. attention coefficients directly from x  (fp32 exact)
    att_direct<<<(NN + 31) / 32, 320>>>(x, pms, pmd, pasrc, padst);

    // 1c. h = x_pad @ W_pad  [N, 780]  (TF32 — h is only used as messages)
    {
        dim3 grid((HIDC + 127) / 128, (NN + 127) / 128);
        tf32_gemm_pipe<false, false><<<grid, 256>>>(pxp, pwp, nullptr, ph, NN, FP, HIDC);
    }

    // 2. CSR build + dinv
    zero_int<<<(NN + 255) / 256, 256>>>(pdeg, NN);
    hist_deg<<<(ET + 255) / 256, 256>>>(ei, pdeg);
    scan_excl<<<1, 1024>>>(pdeg, prowp, NN);
    copy_int<<<(NN + 255) / 256, 256>>>(prowp, pwptr, NN);
    scatter_csr<<<(ET + 255) / 256, 256>>>(ei, pwptr, pcsrc);
    dinv_kernel<<<(NN + 255) / 256, 256>>>(pdeg, pdinv);

    // 3. GAT softmax-aggregate + bias + relu
    gat_agg<<<(NN * 32 + 255) / 256, 256>>>(ph, pasrc, padst, prowp, pcsrc, bgat, pout1);

    // 4. h2 = out1 @ W_gcn   [N, 780]  (pipelined TF32 — dominant GEMM)
    {
        dim3 grid((HIDC + 127) / 128, (NN + 127) / 128);
        tf32_gemm_pipe<false, false><<<grid, 256>>>(pout1, Wgcn, nullptr, ph2, NN, HIDC, HIDC);
    }

    // 5. GCN aggregate + bias + relu
    gcn_agg<<<(NN * 32 + 255) / 256, 256>>>(ph2, pdinv, prowp, pcsrc, bgcn, pout2);

    // 6. graph node ranges (batch is sorted)
    zero_int<<<(GG + 255) / 256, 256>>>(pcnt, GG);
    hist_batch<<<(NN + 255) / 256, 256>>>(batch, pcnt);
    scan_excl<<<1, 1024>>>(pcnt, pgst, GG);

    // 7. mean/max pooling
    pool_kernel<<<GG, 256>>>(pout2, pgst, ppool);

    // 8. fc1 = relu(pooled @ W1 + b1)   (pipelined TF32)
    {
        dim3 grid((P1 + 127) / 128, (GG + 127) / 128);
        tf32_gemm_pipe<true, true><<<grid, 256>>>(ppool, W1, b1, pfc1, GG, PO, P1);
    }

    // 9. out = fc1 @ W2 + b2  (fp32: final layer, small)
    {
        dim3 grid((OC + 127) / 128, (GG + 127) / 128);
        sgemm<true, false><<<grid, 256>>>(pfc1, W2, b2, out, GG, P1, OC);
    }
}

// round 14
// speedup vs baseline: 1.6346x; 1.0883x over previous
#include <cuda_runtime.h>
#include <math.h>
#include <stdint.h>

// Problem constants
constexpr int NN   = 30000;      // nodes
constexpr int EE   = 240000;     // edges (before self loops)
constexpr int GG   = 1000;       // graphs
constexpr int FF   = 78;         // in features
constexpr int FP   = 80;         // padded in features (16B-aligned rows)
constexpr int HH   = 10;         // GAT heads
constexpr int HIDC = 780;        // F*H
constexpr int ET   = EE + NN;    // edges with self loops
constexpr int P1   = 1500;       // fc1 width
constexpr int PO   = 2 * HIDC;   // pooled width 1560
constexpr int OC   = 128;        // output classes
constexpr int H4   = HIDC / 4;   // 195 float4 per feature row

// ---- one big device scratch buffer (no allocations allowed) ----
// Every offset aligned up to 4 floats (16 B) so float4 / cp.async.16 are safe.
constexpr size_t A4(size_t x) { return (x + 3) & ~(size_t)3; }

constexpr size_t OFF_H    = 0;
constexpr size_t OFF_OUT1 = A4(OFF_H    + (size_t)NN * HIDC);
constexpr size_t OFF_H2   = A4(OFF_OUT1 + (size_t)NN * HIDC);
constexpr size_t OFF_OUT2 = A4(OFF_H2   + (size_t)NN * HIDC);
constexpr size_t OFF_ASRC = A4(OFF_OUT2 + (size_t)NN * HIDC);
constexpr size_t OFF_ADST = A4(OFF_ASRC + (size_t)NN * HH);
constexpr size_t OFF_DINV = A4(OFF_ADST + (size_t)NN * HH);
constexpr size_t OFF_POOL = A4(OFF_DINV + NN);
constexpr size_t OFF_FC1  = A4(OFF_POOL + (size_t)GG * PO);
constexpr size_t OFF_DEG  = A4(OFF_FC1  + (size_t)GG * P1);
constexpr size_t OFF_ROWP = A4(OFF_DEG  + NN);
constexpr size_t OFF_WPTR = A4(OFF_ROWP + NN + 1);
constexpr size_t OFF_CSRC = A4(OFF_WPTR + NN);
constexpr size_t OFF_CNT  = A4(OFF_CSRC + ET);
constexpr size_t OFF_GST  = A4(OFF_CNT  + GG);
constexpr size_t OFF_MS   = A4(OFF_GST  + GG + 1);       // M_src [78*10]
constexpr size_t OFF_MD   = A4(OFF_MS   + FF * HH);      // M_dst [78*10]
constexpr size_t OFF_XP   = A4(OFF_MD   + FF * HH);      // x padded [NN*80]
constexpr size_t OFF_WP   = A4(OFF_XP   + (size_t)NN * FP);  // Wgat padded [80*780]
constexpr size_t TOTALF   = OFF_WP   + (size_t)FP * HIDC;

static_assert(OFF_XP % 4 == 0 && OFF_WP % 4 == 0, "16B alignment");

__device__ __align__(16) float g_buf[TOTALF];

// ============================================================
// helpers
// ============================================================
__device__ __forceinline__ uint32_t f2tf32(float v)
{
    uint32_t r;
    asm("cvt.rna.tf32.f32 %0, %1;" : "=r"(r) : "f"(v));
    return r;
}

__device__ __forceinline__ void mma_tf32(float c[4],
                                         const uint32_t a[4],
                                         const uint32_t b[2])
{
    asm volatile(
        "mma.sync.aligned.m16n8k8.row.col.f32.tf32.tf32.f32 "
        "{%0,%1,%2,%3}, {%4,%5,%6,%7}, {%8,%9}, {%0,%1,%2,%3};"
        : "+f"(c[0]), "+f"(c[1]), "+f"(c[2]), "+f"(c[3])
        : "r"(a[0]), "r"(a[1]), "r"(a[2]), "r"(a[3]),
          "r"(b[0]), "r"(b[1]));
}

__device__ __forceinline__ void cp_async16(void* smem_dst, const void* gsrc, int nbytes)
{
    uint32_t d = (uint32_t)__cvta_generic_to_shared(smem_dst);
    asm volatile("cp.async.cg.shared.global [%0], [%1], 16, %2;"
                 :: "r"(d), "l"(gsrc), "r"(nbytes));
}
__device__ __forceinline__ void cp_commit() { asm volatile("cp.async.commit_group;"); }
template<int N> __device__ __forceinline__ void cp_wait()
{ asm volatile("cp.async.wait_group %0;" :: "n"(N)); }

// ============================================================
// Pipelined TF32 GEMM: C[M,Nc] = A[M,K] @ B[K,Nc] (+bias)(+relu)
// 128x128 block tile, BK=16, double-buffered cp.async, 256 thr.
// REQUIRES: K % 4 == 0, Nc % 4 == 0, A and B 16B-aligned.
// Call sites: K in {80, 780, 1560} — all satisfy this.
// ============================================================
template<bool BIAS, bool RELU>
__global__ __launch_bounds__(256, 2)
void tf32_gemm_pipe(const float* __restrict__ A, const float* __restrict__ B,
                    const float* __restrict__ bias, float* __restrict__ C,
                    int M, int K, int Nc)
{
    __shared__ __align__(16) float As[2][128][20];
    __shared__ __align__(16) float Bs[2][16][136];

    const int tid  = threadIdx.x;
    const int warp = tid >> 5, lane = tid & 31;
    const int gid  = lane >> 2, tg = lane & 3;
    const int wr   = warp >> 2, wc = warp & 3;        // 2 x 4 warp grid
    const int m0   = blockIdx.y * 128, n0 = blockIdx.x * 128;

    const int a_row = tid >> 1;            // 0..127
    const int a_c0  = (tid & 1) * 8;       // 0 or 8
    const int b_r   = tid >> 4;            // 0..15
    const int b_c0  = (tid & 15) * 8;      // 0..120

    const int gmA = m0 + a_row;
    const float* a_base = A + (size_t)(gmA < M ? gmA : M - 1) * K;
    const bool a_rowok = (gmA < M);

    float acc[4][4][4];
#pragma unroll
    for (int i = 0; i < 4; i++)
#pragma unroll
        for (int j = 0; j < 4; j++)
#pragma unroll
            for (int k = 0; k < 4; k++) acc[i][j][k] = 0.f;

    const int nk = (K + 15) / 16;

    auto load_tile = [&](int buf, int k0) {
#pragma unroll
        for (int ch = 0; ch < 2; ch++) {
            int c = a_c0 + ch * 4;
            int gk = k0 + c;
            bool ok = a_rowok && (gk + 4 <= K);     // K%4==0: full-or-none
            const float* src = a_base + (gk + 4 <= K ? gk : 0);
            cp_async16(&As[buf][a_row][c], src, ok ? 16 : 0);
        }
        int gkB = k0 + b_r;
        const float* b_base = B + (size_t)(gkB < K ? gkB : K - 1) * Nc;
#pragma unroll
        for (int ch = 0; ch < 2; ch++) {
            int c = b_c0 + ch * 4;
            int gn = n0 + c;
            bool ok = (gkB < K) && (gn + 4 <= Nc);
            const float* src = b_base + (gn + 4 <= Nc ? gn : 0);
            cp_async16(&Bs[buf][b_r][c], src, ok ? 16 : 0);
        }
    };

    load_tile(0, 0);
    cp_commit();

    for (int t = 0; t < nk; t++) {
        int buf = t & 1;
        if (t + 1 < nk) load_tile(buf ^ 1, (t + 1) * 16);
        cp_commit();
        cp_wait<1>();
        __syncthreads();

#pragma unroll
        for (int ks = 0; ks < 16; ks += 8) {
            uint32_t af[4][4];
#pragma unroll
            for (int mt = 0; mt < 4; mt++) {
                int m = wr * 64 + mt * 16;
                af[mt][0] = f2tf32(As[buf][m + gid    ][ks + tg    ]);
                af[mt][1] = f2tf32(As[buf][m + gid + 8][ks + tg    ]);
                af[mt][2] = f2tf32(As[buf][m + gid    ][ks + tg + 4]);
                af[mt][3] = f2tf32(As[buf][m + gid + 8][ks + tg + 4]);
            }
            uint32_t bf[4][2];
#pragma unroll
            for (int nt = 0; nt < 4; nt++) {
                int n = wc * 32 + nt * 8 + gid;
                bf[nt][0] = f2tf32(Bs[buf][ks + tg    ][n]);
                bf[nt][1] = f2tf32(Bs[buf][ks + tg + 4][n]);
            }
#pragma unroll
            for (int mt = 0; mt < 4; mt++)
#pragma unroll
                for (int nt = 0; nt < 4; nt++)
                    mma_tf32(acc[mt][nt], af[mt], bf[nt]);
        }
        __syncthreads();
    }

#pragma unroll
    for (int mt = 0; mt < 4; mt++) {
        int rm = m0 + wr * 64 + mt * 16 + gid;
#pragma unroll
        for (int nt = 0; nt < 4; nt++) {
            int cn = n0 + wc * 32 + nt * 8 + 2 * tg;
#pragma unroll
            for (int half = 0; half < 2; half++) {
                int r = rm + half * 8;
                if (r >= M) continue;
                float v0 = acc[mt][nt][half * 2 + 0];
                float v1 = acc[mt][nt][half * 2 + 1];
                if (cn < Nc) {
                    float v = v0;
                    if (BIAS) v += bias[cn];
                    if (RELU) v = v > 0.f ? v : 0.f;
                    C[(size_t)r * Nc + cn] = v;
                }
                if (cn + 1 < Nc) {
                    float v = v1;
                    if (BIAS) v += bias[cn + 1];
                    if (RELU) v = v > 0.f ? v : 0.f;
                    C[(size_t)r * Nc + cn + 1] = v;
                }
            }
        }
    }
}

// ============================================================
// Generic tiled SGEMM (fp32): final MLP layer only
// ============================================================
template<bool BIAS, bool RELU>
__global__ __launch_bounds__(256)
void sgemm(const float* __restrict__ A, const float* __restrict__ B,
           const float* __restrict__ bias, float* __restrict__ C,
           int M, int K, int Nc)
{
    __shared__ float As[8][128];
    __shared__ float Bs[8][128];

    const int tid = threadIdx.x;
    const int m0 = blockIdx.y * 128;
    const int n0 = blockIdx.x * 128;

    const int a_row = tid >> 1;
    const int a_col = (tid & 1) * 4;
    const int b_row = tid >> 5;
    const int b_col = (tid & 31) * 4;

    const int ty = tid >> 4;
    const int tx = tid & 15;

    float acc[8][8];
#pragma unroll
    for (int i = 0; i < 8; i++)
#pragma unroll
        for (int j = 0; j < 8; j++) acc[i][j] = 0.f;

    for (int k0 = 0; k0 < K; k0 += 8) {
        float av[4];
        const int gm = m0 + a_row;
#pragma unroll
        for (int i = 0; i < 4; i++) {
            int gk = k0 + a_col + i;
            av[i] = (gm < M && gk < K) ? A[(size_t)gm * K + gk] : 0.f;
        }
#pragma unroll
        for (int i = 0; i < 4; i++) As[a_col + i][a_row] = av[i];

        float bv[4];
        const int gk = k0 + b_row;
#pragma unroll
        for (int i = 0; i < 4; i++) {
            int gn = n0 + b_col + i;
            bv[i] = (gk < K && gn < Nc) ? B[(size_t)gk * Nc + gn] : 0.f;
        }
        *(float4*)&Bs[b_row][b_col] = make_float4(bv[0], bv[1], bv[2], bv[3]);

        __syncthreads();

#pragma unroll
        for (int kk = 0; kk < 8; kk++) {
            float4 a0 = *(const float4*)&As[kk][ty * 8];
            float4 a1 = *(const float4*)&As[kk][ty * 8 + 4];
            float4 b0 = *(const float4*)&Bs[kk][tx * 8];
            float4 b1 = *(const float4*)&Bs[kk][tx * 8 + 4];
            float ar[8] = {a0.x, a0.y, a0.z, a0.w, a1.x, a1.y, a1.z, a1.w};
            float br[8] = {b0.x, b0.y, b0.z, b0.w, b1.x, b1.y, b1.z, b1.w};
#pragma unroll
            for (int i = 0; i < 8; i++)
#pragma unroll
                for (int j = 0; j < 8; j++)
                    acc[i][j] = fmaf(ar[i], br[j], acc[i][j]);
        }
        __syncthreads();
    }

#pragma unroll
    for (int i = 0; i < 8; i++) {
        int gm = m0 + ty * 8 + i;
        if (gm >= M) continue;
#pragma unroll
        for (int j = 0; j < 8; j++) {
            int gn = n0 + tx * 8 + j;
            if (gn >= Nc) continue;
            float v = acc[i][j];
            if (BIAS) v += bias[gn];
            if (RELU) v = v > 0.f ? v : 0.f;
            C[(size_t)gm * Nc + gn] = v;
        }
    }
}

// ============================================================
// Pad x [NN,78] -> x_pad [NN,80] (cols 78,79 = 0)
// ============================================================
__global__ __launch_bounds__(256)
void pad_x(const float* __restrict__ x, float* __restrict__ xp)
{
    int i = blockIdx.x * 256 + threadIdx.x;
    if (i >= NN * FP) return;
    int row = i / FP, col = i % FP;
    xp[i] = (col < FF) ? x[(size_t)row * FF + col] : 0.f;
}

// ============================================================
// Pad Wgat [78,780] -> W_pad [80,780] (rows 78,79 = 0)
// ============================================================
__global__ __launch_bounds__(256)
void pad_w(const float* __restrict__ w, float* __restrict__ wp)
{
    int i = blockIdx.x * 256 + threadIdx.x;
    if (i >= FP * HIDC) return;
    int row = i / HIDC;
    wp[i] = (row < FF) ? w[i] : 0.f;
}

// ============================================================
// Fold attention vectors into W_gat (256 thr/block):
// M_src[f*HH + h] = sum_f' W_gat[f, h*FF+f'] * att_src[h, f']
// ============================================================
__global__ __launch_bounds__(256)
void fold_att(const float* __restrict__ Wgat,
              const float* __restrict__ att_s,
              const float* __restrict__ att_d,
              float* __restrict__ Ms, float* __restrict__ Md)
{
    int t = blockIdx.x * 256 + threadIdx.x;
    if (t >= FF * HH) return;
    int f = t / HH, h = t % HH;
    const float* wrow = Wgat + (size_t)f * HIDC + h * FF;
    const float* as = att_s + h * FF;
    const float* ad = att_d + h * FF;
    float s1 = 0.f, s2 = 0.f;
    for (int f2 = 0; f2 < FF; f2++) {
        float w = wrow[f2];
        s1 += w * as[f2];
        s2 += w * ad[f2];
    }
    Ms[f * HH + h] = s1;
    Md[f * HH + h] = s2;
}

// ============================================================
// Attention coefficients directly from x (fp32 exact):
// a_src[n,h] = sum_f x[n,f] * M_src[f,h]; same for dst.
// Block: 320 threads = 32 nodes x 10 heads.
// ============================================================
__global__ __launch_bounds__(320)
void att_direct(const float* __restrict__ x,
                const float* __restrict__ Ms, const float* __restrict__ Md,
                float* __restrict__ asrc, float* __restrict__ adst)
{
    __shared__ float sMs[FF * HH];
    __shared__ float sMd[FF * HH];
    int tid = threadIdx.x;
    for (int i = tid; i < FF * HH; i += 320) {
        sMs[i] = Ms[i];
        sMd[i] = Md[i];
    }
    __syncthreads();

    int n = blockIdx.x * 32 + tid / HH;
    int h = tid % HH;
    if (n >= NN) return;

    const float* xp = x + (size_t)n * FF;
    float s1 = 0.f, s2 = 0.f;
#pragma unroll 6
    for (int f = 0; f < FF; f++) {
        float xv = xp[f];                 // broadcast across the 10 heads
        s1 = fmaf(xv, sMs[f * HH + h], s1);
        s2 = fmaf(xv, sMd[f * HH + h], s2);
    }
    asrc[n * HH + h] = s1;
    adst[n * HH + h] = s2;
}

// ============================================================
// Graph structure kernels
// ============================================================
__global__ __launch_bounds__(256)
void zero_int(int* p, int n)
{
    int i = blockIdx.x * blockDim.x + threadIdx.x;
    if (i < n) p[i] = 0;
}

__global__ __launch_bounds__(256)
void copy_int(const int* __restrict__ a, int* __restrict__ b, int n)
{
    int i = blockIdx.x * blockDim.x + threadIdx.x;
    if (i < n) b[i] = a[i];
}

__global__ __launch_bounds__(256)
void hist_deg(const int* __restrict__ ei, int* __restrict__ deg)
{
    int e = blockIdx.x * blockDim.x + threadIdx.x;
    if (e >= ET) return;
    int d = (e < EE) ? ei[EE + e] : (e - EE);
    atomicAdd(&deg[d], 1);
}

__global__ __launch_bounds__(256)
void hist_batch(const int* __restrict__ batch, int* __restrict__ cnt)
{
    int i = blockIdx.x * blockDim.x + threadIdx.x;
    if (i < NN) atomicAdd(&cnt[batch[i]], 1);
}

// single-block exclusive scan, out has n+1 entries (out[n] = total)
__global__ __launch_bounds__(1024)
void scan_excl(const int* __restrict__ in, int* __restrict__ out, int n)
{
    __shared__ int sh[1024];
    __shared__ int carry;
    if (threadIdx.x == 0) carry = 0;
    __syncthreads();
    for (int base = 0; base < n; base += 1024) {
        int i = base + threadIdx.x;
        int v = (i < n) ? in[i] : 0;
        sh[threadIdx.x] = v;
        __syncthreads();
        for (int off = 1; off < 1024; off <<= 1) {
            int t = (threadIdx.x >= off) ? sh[threadIdx.x - off] : 0;
            __syncthreads();
            sh[threadIdx.x] += t;
            __syncthreads();
        }
        int c0 = carry;
        if (i < n) out[i] = c0 + sh[threadIdx.x] - v;
        __syncthreads();
        if (threadIdx.x == 0) carry = c0 + sh[1023];
        __syncthreads();
    }
    if (threadIdx.x == 0) out[n] = carry;
}

__global__ __launch_bounds__(256)
void scatter_csr(const int* __restrict__ ei, int* __restrict__ wptr,
                 int* __restrict__ csrc)
{
    int e = blockIdx.x * blockDim.x + threadIdx.x;
    if (e >= ET) return;
    int s = (e < EE) ? ei[e] : (e - EE);
    int d = (e < EE) ? ei[EE + e] : (e - EE);
    int pos = atomicAdd(&wptr[d], 1);
    csrc[pos] = s;
}

__global__ __launch_bounds__(256)
void dinv_kernel(const int* __restrict__ deg, float* __restrict__ dinv)
{
    int i = blockIdx.x * blockDim.x + threadIdx.x;
    if (i < NN) dinv[i] = rsqrtf(fmaxf((float)deg[i], 1.f));
}

// ============================================================
// GAT softmax-aggregate: TWO warps per destination node.
// Warp half 0 handles 32-slot blocks {0,2,4,6}, half 1 {1,3,5}.
// Per-output-element arithmetic identical to the 1-warp version.
// ============================================================
__global__ __launch_bounds__(256)
void gat_agg(const float* __restrict__ h, const float* __restrict__ asrc,
             const float* __restrict__ adst, const int* __restrict__ rowptr,
             const int* __restrict__ csrc, const float* __restrict__ bgat,
             float* __restrict__ out1)
{
    __shared__ float wsh[8][HH];
    int gw = (blockIdx.x * 256 + threadIdx.x) >> 5;
    if (gw >= NN * 2) return;
    int lane = threadIdx.x & 31;
    float* myw = wsh[(threadIdx.x >> 5)];
    int d = gw >> 1, half = gw & 1;
    int jb = rowptr[d], je = rowptr[d + 1];

    float ad = (lane < HH) ? adst[d * HH + lane] : 0.f;

    // pass 1: softmax denominator per head (lanes 0..9); each half-warp
    // computes it independently (cheap, avoids cross-warp sync)
    float denom = 0.f;
    for (int j = jb; j < je; j++) {
        int s = csrc[j];
        if (lane < HH) {
            float ev = asrc[s * HH + lane] + ad;
            ev = ev > 0.f ? ev : 0.2f * ev;
            denom += __expf(ev);
        }
    }
    float inv_d = (lane < HH) ? 1.f / denom : 0.f;

    // this warp's 4 float4 slots and per-component head indices
    int tslot[4];
    int4 hd4[4];
#pragma unroll
    for (int k = 0; k < 4; k++) {
        int t = lane + (k * 2 + half) * 32;
        tslot[k] = t;
        int e0 = 4 * ((t < H4) ? t : 0);
        hd4[k] = make_int4(e0 / FF, (e0 + 1) / FF, (e0 + 2) / FF, (e0 + 3) / FF);
    }

    float4 acc[4];
#pragma unroll
    for (int k = 0; k < 4; k++) acc[k] = make_float4(0.f, 0.f, 0.f, 0.f);

    // pass 2: weighted aggregate (float4 gathers)
    for (int j = jb; j < je; j++) {
        int s = csrc[j];
        if (lane < HH) {
            float ev = asrc[s * HH + lane] + ad;
            ev = ev > 0.f ? ev : 0.2f * ev;
            myw[lane] = __expf(ev) * inv_d;
        }
        __syncwarp();
        const float4* hp = (const float4*)(h + (size_t)s * HIDC);
#pragma unroll
        for (int k = 0; k < 4; k++) {
            if (tslot[k] < H4) {
                float4 v = hp[tslot[k]];
                acc[k].x = fmaf(myw[hd4[k].x], v.x, acc[k].x);
                acc[k].y = fmaf(myw[hd4[k].y], v.y, acc[k].y);
                acc[k].z = fmaf(myw[hd4[k].z], v.z, acc[k].z);
                acc[k].w = fmaf(myw[hd4[k].w], v.w, acc[k].w);
            }
        }
        __syncwarp();
    }

    float4* op = (float4*)(out1 + (size_t)d * HIDC);
    const float4* bp = (const float4*)bgat;
#pragma unroll
    for (int k = 0; k < 4; k++) {
        if (tslot[k] < H4) {
            float4 b = bp[tslot[k]];
            float4 v;
            v.x = fmaxf(acc[k].x + b.x, 0.f);
            v.y = fmaxf(acc[k].y + b.y, 0.f);
            v.z = fmaxf(acc[k].z + b.z, 0.f);
            v.w = fmaxf(acc[k].w + b.w, 0.f);
            op[tslot[k]] = v;
        }
    }
}

// ============================================================
// GCN normalized aggregate: TWO warps per destination node.
// ============================================================
__global__ __launch_bounds__(256)
void gcn_agg(const float* __restrict__ h2, const float* __restrict__ dinv,
             const int* __restrict__ rowptr, const int* __restrict__ csrc,
             const float* __restrict__ bgcn, float* __restrict__ out2)
{
    int gw = (blockIdx.x * 256 + threadIdx.x) >> 5;
    if (gw >= NN * 2) return;
    int lane = threadIdx.x & 31;
    int d = gw >> 1, half = gw & 1;
    int jb = rowptr[d], je = rowptr[d + 1];
    float dd = dinv[d];

    int tslot[4];
#pragma unroll
    for (int k = 0; k < 4; k++) tslot[k] = lane + (k * 2 + half) * 32;

    float4 acc[4];
#pragma unroll
    for (int k = 0; k < 4; k++) acc[k] = make_float4(0.f, 0.f, 0.f, 0.f);

    for (int j = jb; j < je; j++) {
        int s = csrc[j];
        float w = dinv[s] * dd;
        const float4* hp = (const float4*)(h2 + (size_t)s * HIDC);
#pragma unroll
        for (int k = 0; k < 4; k++) {
            if (tslot[k] < H4) {
                float4 v = hp[tslot[k]];
                acc[k].x = fmaf(w, v.x, acc[k].x);
                acc[k].y = fmaf(w, v.y, acc[k].y);
                acc[k].z = fmaf(w, v.z, acc[k].z);
                acc[k].w = fmaf(w, v.w, acc[k].w);
            }
        }
    }

    float4* op = (float4*)(out2 + (size_t)d * HIDC);
    const float4* bp = (const float4*)bgcn;
#pragma unroll
    for (int k = 0; k < 4; k++) {
        if (tslot[k] < H4) {
            float4 b = bp[tslot[k]];
            float4 v;
            v.x = fmaxf(acc[k].x + b.x, 0.f);
            v.y = fmaxf(acc[k].y + b.y, 0.f);
            v.z = fmaxf(acc[k].z + b.z, 0.f);
            v.w = fmaxf(acc[k].w + b.w, 0.f);
            op[tslot[k]] = v;
        }
    }
}

// ============================================================
// Global mean/max pool, block per graph (batch is sorted), float4
// ============================================================
__global__ __launch_bounds__(256)
void pool_kernel(const float* __restrict__ out2, const int* __restrict__ gstart,
                 float* __restrict__ pooled)
{
    int g = blockIdx.x;
    int t = threadIdx.x;          // one float4 slot per thread (195 < 256)
    int start = gstart[g];
    int cnt = gstart[g + 1] - start;

    if (t >= H4) return;

    float4 s = make_float4(0.f, 0.f, 0.f, 0.f);
    float4 mx = make_float4(-INFINITY, -INFINITY, -INFINITY, -INFINITY);

    for (int i = 0; i < cnt; i++) {
        const float4* p = (const float4*)(out2 + (size_t)(start + i) * HIDC);
        float4 v = p[t];
        s.x += v.x; s.y += v.y; s.z += v.z; s.w += v.w;
        mx.x = fmaxf(mx.x, v.x); mx.y = fmaxf(mx.y, v.y);
        mx.z = fmaxf(mx.z, v.z); mx.w = fmaxf(mx.w, v.w);
    }
    float inv = 1.f / fmaxf((float)cnt, 1.f);
    float4 mean = make_float4(s.x * inv, s.y * inv, s.z * inv, s.w * inv);
    if (cnt <= 0) mx = make_float4(0.f, 0.f, 0.f, 0.f);

    float4* pm = (float4*)(pooled + (size_t)g * PO);
    float4* px = (float4*)(pooled + (size_t)g * PO + HIDC);
    pm[t] = mean;
    px[t] = mx;
}

// ============================================================
// Launch
// ============================================================
extern "C" void kernel_launch(void* const* d_in, const int* in_sizes, int n_in,
                              void* d_out, int out_size)
{
    const float* x     = (const float*)d_in[0];
    const int*   ei    = (const int*)  d_in[1];
    const int*   batch = (const int*)  d_in[2];
    const float* Wgat  = (const float*)d_in[3];
    const float* att_s = (const float*)d_in[4];
    const float* att_d = (const float*)d_in[5];
    const float* bgat  = (const float*)d_in[6];
    const float* Wgcn  = (const float*)d_in[7];
    const float* bgcn  = (const float*)d_in[8];
    const float* W1    = (const float*)d_in[9];
    const float* b1    = (const float*)d_in[10];
    const float* W2    = (const float*)d_in[11];
    const float* b2    = (const float*)d_in[12];
    float* out = (float*)d_out;

    float* base = nullptr;
    cudaGetSymbolAddress((void**)&base, g_buf);

    float* ph     = base + OFF_H;
    float* pout1  = base + OFF_OUT1;
    float* ph2    = base + OFF_H2;
    float* pout2  = base + OFF_OUT2;
    float* pasrc  = base + OFF_ASRC;
    float* padst  = base + OFF_ADST;
    float* pdinv  = base + OFF_DINV;
    float* ppool  = base + OFF_POOL;
    float* pfc1   = base + OFF_FC1;
    float* pms    = base + OFF_MS;
    float* pmd    = base + OFF_MD;
    float* pxp    = base + OFF_XP;
    float* pwp    = base + OFF_WP;
    int*   pdeg   = (int*)(base + OFF_DEG);
    int*   prowp  = (int*)(base + OFF_ROWP);
    int*   pwptr  = (int*)(base + OFF_WPTR);
    int*   pcsrc  = (int*)(base + OFF_CSRC);
    int*   pcnt   = (int*)(base + OFF_CNT);
    int*   pgst   = (int*)(base + OFF_GST);

    // 0. pad x -> [NN,80] and Wgat -> [80,780] for 16B-aligned cp.async
    pad_x<<<(NN * FP + 255) / 256, 256>>>(x, pxp);
    pad_w<<<(FP * HIDC + 255) / 256, 256>>>(Wgat, pwp);

    // 1a. fold attention vectors: M_src/M_dst [78,10]  (fp32 exact, tiny)
    fold_att<<<(FF * HH + 255) / 256, 256>>>(Wgat, att_s, att_d, pms, pmd);

    // 1b. attention coefficients directly from x  (fp32 exact)
    att_direct<<<(NN + 31) / 32, 320>>>(x, pms, pmd, pasrc, padst);

    // 1c. h = x_pad @ W_pad  [N, 780]  (TF32 — h is only used as messages)
    {
        dim3 grid((HIDC + 127) / 128, (NN + 127) / 128);
        tf32_gemm_pipe<false, false><<<grid, 256>>>(pxp, pwp, nullptr, ph, NN, FP, HIDC);
    }

    // 2. CSR build + dinv
    zero_int<<<(NN + 255) / 256, 256>>>(pdeg, NN);
    hist_deg<<<(ET + 255) / 256, 256>>>(ei, pdeg);
    scan_excl<<<1, 1024>>>(pdeg, prowp, NN);
    copy_int<<<(NN + 255) / 256, 256>>>(prowp, pwptr, NN);
    scatter_csr<<<(ET + 255) / 256, 256>>>(ei, pwptr, pcsrc);
    dinv_kernel<<<(NN + 255) / 256, 256>>>(pdeg, pdinv);

    // 3. GAT softmax-aggregate + bias + relu  (2 warps per node)
    gat_agg<<<(NN * 2 * 32 + 255) / 256, 256>>>(ph, pasrc, padst, prowp, pcsrc, bgat, pout1);

    // 4. h2 = out1 @ W_gcn   [N, 780]  (pipelined TF32 — dominant GEMM)
    {
        dim3 grid((HIDC + 127) / 128, (NN + 127) / 128);
        tf32_gemm_pipe<false, false><<<grid, 256>>>(pout1, Wgcn, nullptr, ph2, NN, HIDC, HIDC);
    }

    // 5. GCN aggregate + bias + relu  (2 warps per node)
    gcn_agg<<<(NN * 2 * 32 + 255) / 256, 256>>>(ph2, pdinv, prowp, pcsrc, bgcn, pout2);

    // 6. graph node ranges (batch is sorted)
    zero_int<<<(GG + 255) / 256, 256>>>(pcnt, GG);
    hist_batch<<<(NN + 255) / 256, 256>>>(batch, pcnt);
    scan_excl<<<1, 1024>>>(pcnt, pgst, GG);

    // 7. mean/max pooling
    pool_kernel<<<GG, 256>>>(pout2, pgst, ppool);

    // 8. fc1 = relu(pooled @ W1 + b1)   (pipelined TF32)
    {
        dim3 grid((P1 + 127) / 128, (GG + 127) / 128);
        tf32_gemm_pipe<true, true><<<grid, 256>>>(ppool, W1, b1, pfc1, GG, PO, P1);
    }

    // 9. out = fc1 @ W2 + b2  (fp32: final layer, small)
    {
        dim3 grid((OC + 127) / 128, (GG + 127) / 128);
        sgemm<true, false><<<grid, 256>>>(pfc1, W2, b2, out, GG, P1, OC);
    }
}